// round 2
// baseline (speedup 1.0000x reference)
#include <cuda_runtime.h>
#include <math.h>

#define B 4096
#define D 128
#define NT 32              // 4096 / 128 tiles per dimension
#define NCLS 64

// ---- scratch (device globals; no allocation allowed) ----
__device__ float  g_dist[(size_t)B * (size_t)B];   // upper-tile region valid
__device__ float  g_rowneg[B];
__device__ float  g_mag[B];
__device__ int    g_t32[B];
__device__ int    g_hist[NCLS];
__device__ double g_loss;

// ---------------------------------------------------------------------------
// K0: zero accumulators (graph replays: must reset every launch)
// ---------------------------------------------------------------------------
__global__ void k_init() {
    int idx = blockIdx.x * blockDim.x + threadIdx.x;
    if (idx < B)    g_rowneg[idx] = 0.f;
    if (idx < NCLS) g_hist[idx] = 0;
    if (idx == 0)   g_loss = 0.0;
}

// ---------------------------------------------------------------------------
// K1: per-row squared magnitude + int32 labels + label histogram
// one warp per row; 8 warps / block.  NOTE: targets are int32 (JAX x64 off).
// ---------------------------------------------------------------------------
__global__ void __launch_bounds__(256) k_mag(const float* __restrict__ X,
                                             const int* __restrict__ T) {
    int warp = threadIdx.x >> 5;
    int lane = threadIdx.x & 31;
    int row  = blockIdx.x * 8 + warp;
    const float4* xr = (const float4*)(X + (size_t)row * D);
    float4 v = xr[lane];
    float s = v.x * v.x + v.y * v.y + v.z * v.z + v.w * v.w;
    #pragma unroll
    for (int off = 16; off; off >>= 1) s += __shfl_xor_sync(0xffffffff, s, off);
    if (lane == 0) {
        g_mag[row] = s;
        int t = T[row];
        g_t32[row] = t;
        atomicAdd(&g_hist[t & (NCLS - 1)], 1);   // mask: never fault on bad dtype
    }
}

// ---------------------------------------------------------------------------
// K2: symmetric tiled dist GEMM + fused epilogue
//   128x128 output tile / block, 256 threads, 8x8 register blocking,
//   K chunked 4x32, smem stored TRANSPOSED [k][m] (conflict-free frag loads).
//   Only upper-triangular tiles (bi <= bj): 528 blocks.
// ---------------------------------------------------------------------------
__global__ void __launch_bounds__(256) k_dist(const float* __restrict__ X) {
    __shared__ float As[32][128];
    __shared__ float Bs[32][128];
    __shared__ float rbuf[128];
    __shared__ float cbuf[128];

    int tid = threadIdx.x;

    // decode triangular block index -> (bi, bj), bi <= bj
    int idx = blockIdx.x;
    int bi = 0, rem = idx;
    while (rem >= NT - bi) { rem -= NT - bi; bi++; }
    int bj = bi + rem;

    int tx = tid & 15, ty = tid >> 4;

    float acc[8][8];
    #pragma unroll
    for (int ii = 0; ii < 8; ii++)
        #pragma unroll
        for (int jj = 0; jj < 8; jj++) acc[ii][jj] = 0.f;

    const float4* Xv = (const float4*)X;

    for (int c = 0; c < 4; ++c) {          // K chunks of 32
        // transposed fill: e = kc*128 + r ; smem stores conflict-free
        #pragma unroll
        for (int f = 0; f < 4; f++) {
            int e  = tid + 256 * f;        // 0..1023
            int r  = e & 127;              // tile row
            int kc = e >> 7;               // float4 chunk within K-32 (0..7)
            float4 va = Xv[(size_t)(bi * 128 + r) * 32 + c * 8 + kc];
            float4 vb = Xv[(size_t)(bj * 128 + r) * 32 + c * 8 + kc];
            As[kc * 4 + 0][r] = va.x; As[kc * 4 + 1][r] = va.y;
            As[kc * 4 + 2][r] = va.z; As[kc * 4 + 3][r] = va.w;
            Bs[kc * 4 + 0][r] = vb.x; Bs[kc * 4 + 1][r] = vb.y;
            Bs[kc * 4 + 2][r] = vb.z; Bs[kc * 4 + 3][r] = vb.w;
        }
        __syncthreads();

        #pragma unroll 8
        for (int kk = 0; kk < 32; ++kk) {
            float4 a0 = *(const float4*)&As[kk][ty * 8];
            float4 a1 = *(const float4*)&As[kk][ty * 8 + 4];
            float4 b0 = *(const float4*)&Bs[kk][tx * 8];
            float4 b1 = *(const float4*)&Bs[kk][tx * 8 + 4];
            float a[8] = {a0.x, a0.y, a0.z, a0.w, a1.x, a1.y, a1.z, a1.w};
            float b[8] = {b0.x, b0.y, b0.z, b0.w, b1.x, b1.y, b1.z, b1.w};
            #pragma unroll
            for (int ii = 0; ii < 8; ii++)
                #pragma unroll
                for (int jj = 0; jj < 8; jj++)
                    acc[ii][jj] += a[ii] * b[jj];
        }
        __syncthreads();
    }

    // --- epilogue ---
    int i0 = bi * 128, j0 = bj * 128;
    float magi[8], magj[8];
    int   ti[8], tj[8];
    #pragma unroll
    for (int ii = 0; ii < 8; ii++) {
        int gi = i0 + ty * 8 + ii;
        magi[ii] = g_mag[gi]; ti[ii] = g_t32[gi];
    }
    #pragma unroll
    for (int jj = 0; jj < 8; jj++) {
        int gj = j0 + tx * 8 + jj;
        magj[jj] = g_mag[gj]; tj[jj] = g_t32[gj];
    }

    float rowsum[8] = {0, 0, 0, 0, 0, 0, 0, 0};
    float colsum[8] = {0, 0, 0, 0, 0, 0, 0, 0};

    #pragma unroll
    for (int ii = 0; ii < 8; ii++) {
        float dline[8];
        #pragma unroll
        for (int jj = 0; jj < 8; jj++) {
            float d2 = magi[ii] + magj[jj] - 2.f * acc[ii][jj];
            float dist = d2 > 0.f ? sqrtf(d2) : 0.f;
            dline[jj] = dist;
            float e = (ti[ii] != tj[jj]) ? __expf(1.0f - dist) : 0.f;
            rowsum[ii] += e;
            colsum[jj] += e;
        }
        size_t base = (size_t)(i0 + ty * 8 + ii) * B + (size_t)(j0 + tx * 8);
        float4* dst = (float4*)(g_dist + base);
        dst[0] = make_float4(dline[0], dline[1], dline[2], dline[3]);
        dst[1] = make_float4(dline[4], dline[5], dline[6], dline[7]);
    }

    // reduce rowsum across the 16 tx lanes (same ty) via shfl
    #pragma unroll
    for (int ii = 0; ii < 8; ii++) {
        #pragma unroll
        for (int off = 1; off < 16; off <<= 1)
            rowsum[ii] += __shfl_xor_sync(0xffffffff, rowsum[ii], off);
    }
    // combine colsum across the two ty values within each warp
    #pragma unroll
    for (int jj = 0; jj < 8; jj++)
        colsum[jj] += __shfl_xor_sync(0xffffffff, colsum[jj], 16);

    if (tid < 128) { rbuf[tid] = 0.f; cbuf[tid] = 0.f; }
    __syncthreads();

    if (tx == 0) {                    // one lane per ty holds full row sum
        #pragma unroll
        for (int ii = 0; ii < 8; ii++)
            atomicAdd(&rbuf[ty * 8 + ii], rowsum[ii]);
    }
    if ((ty & 1) == 0) {              // even-ty lanes hold per-warp col sums
        #pragma unroll
        for (int jj = 0; jj < 8; jj++)
            atomicAdd(&cbuf[tx * 8 + jj], colsum[jj]);
    }
    __syncthreads();

    if (tid < 128) {
        atomicAdd(&g_rowneg[i0 + tid], rbuf[tid]);
        if (bi != bj)                 // diag tile: row sums already cover all
            atomicAdd(&g_rowneg[j0 + tid], cbuf[tid]);
    }
}

// ---------------------------------------------------------------------------
// K3: positive pairs (i<j, same label): hinge^2 sum
// one block = 256 consecutive j of one row i; 16 blocks per row
// ---------------------------------------------------------------------------
__global__ void __launch_bounds__(256) k_loss() {
    int i      = blockIdx.x >> 4;
    int jbase  = (blockIdx.x & 15) << 8;
    if (jbase + 255 <= i) return;     // block entirely in lower triangle

    int j = jbase + threadIdx.x;
    float h2 = 0.f;
    if (j > i && g_t32[i] == g_t32[j]) {
        float dist = g_dist[(size_t)i * B + j];
        float l = logf(g_rowneg[i] + g_rowneg[j]) + dist;
        if (l > 0.f) h2 = l * l;
    }

    float s = h2;
    #pragma unroll
    for (int off = 16; off; off >>= 1) s += __shfl_xor_sync(0xffffffff, s, off);
    __shared__ float ws[8];
    if ((threadIdx.x & 31) == 0) ws[threadIdx.x >> 5] = s;
    __syncthreads();
    if (threadIdx.x < 8) {
        s = ws[threadIdx.x];
        #pragma unroll
        for (int off = 4; off; off >>= 1) s += __shfl_xor_sync(0xff, s, off);
        if (threadIdx.x == 0 && s != 0.f) atomicAdd(&g_loss, (double)s);
    }
}

// ---------------------------------------------------------------------------
// K4: counter = sum_c n_c*(n_c-1)/2 ; out = loss / (2*counter)
// ---------------------------------------------------------------------------
__global__ void k_final(float* __restrict__ out) {
    __shared__ long long cnt[NCLS];
    int t = threadIdx.x;
    long long n = (long long)g_hist[t];
    cnt[t] = n * (n - 1) / 2;
    __syncthreads();
    if (t == 0) {
        long long total = 0;
        #pragma unroll
        for (int c = 0; c < NCLS; c++) total += cnt[c];
        out[0] = (float)(g_loss / (2.0 * (double)total));
    }
}

// ---------------------------------------------------------------------------
extern "C" void kernel_launch(void* const* d_in, const int* in_sizes, int n_in,
                              void* d_out, int out_size) {
    const float* X   = (const float*)d_in[0];
    const int*   T   = (const int*)d_in[1];      // int32: JAX x64 disabled
    float*       out = (float*)d_out;

    k_init<<<16, 256>>>();
    k_mag<<<B / 8, 256>>>(X, T);
    k_dist<<<NT * (NT + 1) / 2, 256>>>(X);
    k_loss<<<B * (B / 256), 256>>>();
    k_final<<<1, NCLS>>>(out);
}